// round 3
// baseline (speedup 1.0000x reference)
#include <cuda_runtime.h>
#include <math.h>

// Problem constants
#define D_  768
#define H_  12
#define E_  64
#define S_  2000
#define MQ  2048    // B*L*TQ
#define BLn 256     // B*L
#define TQn 8

// Scratch (device globals: allocation-free)
__device__ float g_Xq[MQ * D_];
__device__ float g_Xk[S_ * D_];
__device__ float g_Xv[S_ * D_];
__device__ float g_Qb[MQ * D_];
__device__ float g_Kb[S_ * D_];
__device__ float g_Vb[S_ * D_];
__device__ float g_Ob[MQ * D_];
__device__ float g_Pool[BLn * D_];

// ---------------------------------------------------------------------------
// helpers
// ---------------------------------------------------------------------------
__device__ __forceinline__ unsigned f2tf(float x) {
    unsigned r;
    asm("cvt.rna.tf32.f32 %0, %1;" : "=r"(r) : "f"(x));
    return r;
}

__device__ __forceinline__ void mma_tf32(float* d, const unsigned* a,
                                         unsigned b0, unsigned b1) {
    asm volatile(
        "mma.sync.aligned.m16n8k8.row.col.f32.tf32.tf32.f32 "
        "{%0,%1,%2,%3},{%4,%5,%6,%7},{%8,%9},{%0,%1,%2,%3};\n"
        : "+f"(d[0]), "+f"(d[1]), "+f"(d[2]), "+f"(d[3])
        : "r"(a[0]), "r"(a[1]), "r"(a[2]), "r"(a[3]), "r"(b0), "r"(b1));
}

// Paired-k layout: within each k-octet, order is (0,4,1,5,2,6,3,7).
// For a 4-aligned base e4 (covering k = e4..e4+3, all in the same half of an
// octet), the smem position of element j is pkBase(e4) + 2*j.
__device__ __forceinline__ int pkBase(int e4) {
    return (e4 & ~7) + ((e4 & 4) ? 1 : 0);
}
// Position of a single index s inside paired-k layout.
__device__ __forceinline__ int pkPos(int s) {
    int w = s & 7;
    return (s & ~7) + ((w < 4) ? (w << 1) : (((w - 4) << 1) | 1));
}

// ---------------------------------------------------------------------------
// LayerNorm
// ---------------------------------------------------------------------------
__global__ void ln_kernel(const float* __restrict__ x, float* __restrict__ y,
                          const float* __restrict__ g, const float* __restrict__ b) {
    int row = blockIdx.x;
    const float* xr = x + (size_t)row * D_;
    int t = threadIdx.x;
    float v0 = xr[t], v1 = xr[t + 256], v2 = xr[t + 512];
    float s  = v0 + v1 + v2;
    float ss = v0 * v0 + v1 * v1 + v2 * v2;

    __shared__ float redS[8], redQ[8];
    #pragma unroll
    for (int o = 16; o > 0; o >>= 1) {
        s  += __shfl_xor_sync(0xffffffffu, s, o);
        ss += __shfl_xor_sync(0xffffffffu, ss, o);
    }
    int warp = t >> 5, lane = t & 31;
    if (lane == 0) { redS[warp] = s; redQ[warp] = ss; }
    __syncthreads();
    float sum = 0.f, sq = 0.f;
    #pragma unroll
    for (int w = 0; w < 8; w++) { sum += redS[w]; sq += redQ[w]; }

    float mean = sum * (1.0f / D_);
    float var  = sq * (1.0f / D_) - mean * mean;
    float rs   = rsqrtf(var + 1e-5f);

    float* yr = y + (size_t)row * D_;
    yr[t]       = (v0 - mean) * rs * g[t]       + b[t];
    yr[t + 256] = (v1 - mean) * rs * g[t + 256] + b[t + 256];
    yr[t + 512] = (v2 - mean) * rs * g[t + 512] + b[t + 512];
}

// ---------------------------------------------------------------------------
// Batched TF32 GEMM: C[M][768] = A[M][768] @ W^T + bias
// CTA 128x128, BK=32 (paired-k layout, LD=40), 256 threads, warp tile 64x32.
// ---------------------------------------------------------------------------
#define GLD 40
__global__ __launch_bounds__(256, 2)
void gemm3_tf32(const float* A0, const float* W0, const float* bi0, float* C0, int M0,
                const float* A1, const float* W1, const float* bi1, float* C1, int M1,
                const float* A2, const float* W2, const float* bi2, float* C2, int M2) {
    const float* A; const float* W; const float* bias; float* C; int M;
    if (blockIdx.z == 0) { A = A0; W = W0; bias = bi0; C = C0; M = M0; }
    else if (blockIdx.z == 1) { A = A1; W = W1; bias = bi1; C = C1; M = M1; }
    else { A = A2; W = W2; bias = bi2; C = C2; M = M2; }

    __shared__ unsigned As[128 * GLD];
    __shared__ unsigned Ws[128 * GLD];

    int t = threadIdx.x, w = t >> 5, lane = t & 31;
    int g = lane >> 2, c = lane & 3;
    int wm = w >> 2, wn = w & 3;
    int row0 = blockIdx.y * 128;
    int col0 = blockIdx.x * 128;

    float acc[4][4][4];
    #pragma unroll
    for (int i = 0; i < 4; i++)
        #pragma unroll
        for (int j = 0; j < 4; j++)
            #pragma unroll
            for (int k = 0; k < 4; k++) acc[i][j][k] = 0.f;

    for (int k0 = 0; k0 < D_; k0 += 32) {
        __syncthreads();
        #pragma unroll
        for (int i = t; i < 1024; i += 256) {
            int r = i >> 3, kq = (i & 7) << 2;
            int base = r * GLD + pkBase(kq);
            int ar = row0 + r;
            float4 av = make_float4(0.f, 0.f, 0.f, 0.f);
            if (ar < M) av = *(const float4*)(A + (size_t)ar * D_ + k0 + kq);
            As[base + 0] = f2tf(av.x); As[base + 2] = f2tf(av.y);
            As[base + 4] = f2tf(av.z); As[base + 6] = f2tf(av.w);

            float4 wv = *(const float4*)(W + (size_t)(col0 + r) * D_ + k0 + kq);
            Ws[base + 0] = f2tf(wv.x); Ws[base + 2] = f2tf(wv.y);
            Ws[base + 4] = f2tf(wv.z); Ws[base + 6] = f2tf(wv.w);
        }
        __syncthreads();

        #pragma unroll
        for (int ks = 0; ks < 4; ks++) {
            int kk = ks * 8 + 2 * c;
            unsigned a[4][4];
            #pragma unroll
            for (int mt = 0; mt < 4; mt++) {
                int base = wm * 64 + mt * 16;
                uint2 lo = *(const uint2*)&As[(base + g)     * GLD + kk];
                uint2 hi = *(const uint2*)&As[(base + g + 8) * GLD + kk];
                a[mt][0] = lo.x; a[mt][1] = hi.x; a[mt][2] = lo.y; a[mt][3] = hi.y;
            }
            #pragma unroll
            for (int nt = 0; nt < 4; nt++) {
                int n = wn * 32 + nt * 8 + g;
                uint2 b = *(const uint2*)&Ws[n * GLD + kk];
                #pragma unroll
                for (int mt = 0; mt < 4; mt++)
                    mma_tf32(acc[mt][nt], a[mt], b.x, b.y);
            }
        }
    }

    #pragma unroll
    for (int mt = 0; mt < 4; mt++) {
        int rA = row0 + wm * 64 + mt * 16 + g;
        int rB = rA + 8;
        #pragma unroll
        for (int nt = 0; nt < 4; nt++) {
            int colb = col0 + wn * 32 + nt * 8 + 2 * c;
            float b0v = bias[colb], b1v = bias[colb + 1];
            if (rA < M) {
                C[(size_t)rA * D_ + colb]     = acc[mt][nt][0] + b0v;
                C[(size_t)rA * D_ + colb + 1] = acc[mt][nt][1] + b1v;
            }
            if (rB < M) {
                C[(size_t)rB * D_ + colb]     = acc[mt][nt][2] + b0v;
                C[(size_t)rB * D_ + colb + 1] = acc[mt][nt][3] + b1v;
            }
        }
    }
}

// ---------------------------------------------------------------------------
// TF32 flash attention, occ-2 version.
// Per CTA: 128 query rows x head h. 8 warps, each warp owns 16 rows.
// SC=64 bank chunk, online softmax with quad-local reductions only.
// grid: (MQ/128, 12) = 192 CTAs, 256 threads, smem 110.8 KB (occ 2).
// Layouts (paired-k, LD=72): Qs[q][k], Ks[s][k], Vt[e][s], Ps[q][s].
// ---------------------------------------------------------------------------
#define AQT 128
#define ASC 64
#define ALD 72
#define ATTN_WORDS (AQT*ALD + ASC*ALD + E_*ALD + AQT*ALD + ASC)
#define ATTN_SMEM  (ATTN_WORDS * 4)

__global__ __launch_bounds__(256, 2)
void attn_tf32(const float* __restrict__ Q, const float* __restrict__ K,
               const float* __restrict__ V, const int* __restrict__ mask,
               float* __restrict__ O) {
    extern __shared__ unsigned smu[];
    unsigned* Qs = smu;                        // [128][72]
    unsigned* Ks = Qs + AQT * ALD;             // [64][72]
    unsigned* Vt = Ks + ASC * ALD;             // [64 e][72]  (s paired)
    unsigned* Ps = Vt + E_ * ALD;              // [128][72]
    float* maskAdd = (float*)(Ps + AQT * ALD); // [64]

    int h = blockIdx.y;
    int row0 = blockIdx.x * AQT;
    int t = threadIdx.x, w = t >> 5, lane = t & 31;
    int g = lane >> 2, c = lane & 3;
    int wrow = w * 16;

    // load Q tile (tf32, paired-k)
    #pragma unroll 2
    for (int i = t; i < AQT * 16; i += 256) {
        int r = i >> 4, e4 = (i & 15) << 2;
        float4 q4 = *(const float4*)(Q + (size_t)(row0 + r) * D_ + h * E_ + e4);
        int base = r * ALD + pkBase(e4);
        Qs[base + 0] = f2tf(q4.x); Qs[base + 2] = f2tf(q4.y);
        Qs[base + 4] = f2tf(q4.z); Qs[base + 6] = f2tf(q4.w);
    }

    float mA = -1e30f, mB = -1e30f, lA = 0.f, lB = 0.f;
    float acc[8][4];
    #pragma unroll
    for (int nt = 0; nt < 8; nt++)
        #pragma unroll
        for (int k = 0; k < 4; k++) acc[nt][k] = 0.f;

    const int nChunks = (S_ + ASC - 1) / ASC;   // 32
    for (int ch = 0; ch < nChunks; ch++) {
        int s0 = ch * ASC;
        __syncthreads();

        // stage K (paired-k) and V transposed (paired-s); zero tail
        #pragma unroll 2
        for (int i = t; i < ASC * 16; i += 256) {
            int s = i >> 4, e4 = (i & 15) << 2;
            int gs = s0 + s;
            float4 kv = make_float4(0.f, 0.f, 0.f, 0.f);
            float4 vv = make_float4(0.f, 0.f, 0.f, 0.f);
            if (gs < S_) {
                kv = *(const float4*)(K + (size_t)gs * D_ + h * E_ + e4);
                vv = *(const float4*)(V + (size_t)gs * D_ + h * E_ + e4);
            }
            int kb = s * ALD + pkBase(e4);
            Ks[kb + 0] = f2tf(kv.x); Ks[kb + 2] = f2tf(kv.y);
            Ks[kb + 4] = f2tf(kv.z); Ks[kb + 6] = f2tf(kv.w);
            int sp = pkPos(s);
            Vt[(e4 + 0) * ALD + sp] = f2tf(vv.x);
            Vt[(e4 + 1) * ALD + sp] = f2tf(vv.y);
            Vt[(e4 + 2) * ALD + sp] = f2tf(vv.z);
            Vt[(e4 + 3) * ALD + sp] = f2tf(vv.w);
        }
        if (t < ASC) {
            int gs = s0 + t;
            maskAdd[t] = (gs < S_ && mask[gs] != 0) ? 0.f : -1e30f;
        }
        __syncthreads();

        // ---- scores = Q @ K^T ----
        float sc[8][4];
        #pragma unroll
        for (int nt = 0; nt < 8; nt++)
            #pragma unroll
            for (int k = 0; k < 4; k++) sc[nt][k] = 0.f;

        #pragma unroll
        for (int ks = 0; ks < 8; ks++) {
            int kk = ks * 8 + 2 * c;
            unsigned a[4];
            uint2 lo = *(const uint2*)&Qs[(wrow + g)     * ALD + kk];
            uint2 hi = *(const uint2*)&Qs[(wrow + g + 8) * ALD + kk];
            a[0] = lo.x; a[1] = hi.x; a[2] = lo.y; a[3] = hi.y;
            #pragma unroll
            for (int nt = 0; nt < 8; nt++) {
                uint2 b = *(const uint2*)&Ks[(nt * 8 + g) * ALD + kk];
                mma_tf32(sc[nt], a, b.x, b.y);
            }
        }

        // ---- online softmax (rows g and g+8 within quad) ----
        {
            float mxA = -1e30f, mxB = -1e30f;
            #pragma unroll
            for (int nt = 0; nt < 8; nt++) {
                int j0 = nt * 8 + 2 * c;
                float ma0 = maskAdd[j0], ma1 = maskAdd[j0 + 1];
                sc[nt][0] = sc[nt][0] * 0.125f + ma0;
                sc[nt][1] = sc[nt][1] * 0.125f + ma1;
                sc[nt][2] = sc[nt][2] * 0.125f + ma0;
                sc[nt][3] = sc[nt][3] * 0.125f + ma1;
                mxA = fmaxf(mxA, fmaxf(sc[nt][0], sc[nt][1]));
                mxB = fmaxf(mxB, fmaxf(sc[nt][2], sc[nt][3]));
            }
            mxA = fmaxf(mxA, __shfl_xor_sync(0xffffffffu, mxA, 1));
            mxA = fmaxf(mxA, __shfl_xor_sync(0xffffffffu, mxA, 2));
            mxB = fmaxf(mxB, __shfl_xor_sync(0xffffffffu, mxB, 1));
            mxB = fmaxf(mxB, __shfl_xor_sync(0xffffffffu, mxB, 2));

            float mnA = fmaxf(mA, mxA);
            float mnB = fmaxf(mB, mxB);
            float corrA = __expf(mA - mnA);
            float corrB = __expf(mB - mnB);
            mA = mnA; mB = mnB;

            int rowA = wrow + g, rowB = rowA + 8;
            float psA = 0.f, psB = 0.f;
            #pragma unroll
            for (int nt = 0; nt < 8; nt++) {
                int j0 = nt * 8 + 2 * c;
                float p0 = __expf(sc[nt][0] - mnA);
                float p1 = __expf(sc[nt][1] - mnA);
                float p2 = __expf(sc[nt][2] - mnB);
                float p3 = __expf(sc[nt][3] - mnB);
                psA += p0 + p1; psB += p2 + p3;
                int q0 = pkPos(j0), q1 = pkPos(j0 + 1);
                Ps[rowA * ALD + q0] = f2tf(p0);
                Ps[rowA * ALD + q1] = f2tf(p1);
                Ps[rowB * ALD + q0] = f2tf(p2);
                Ps[rowB * ALD + q1] = f2tf(p3);
            }
            psA += __shfl_xor_sync(0xffffffffu, psA, 1);
            psA += __shfl_xor_sync(0xffffffffu, psA, 2);
            psB += __shfl_xor_sync(0xffffffffu, psB, 1);
            psB += __shfl_xor_sync(0xffffffffu, psB, 2);
            lA = lA * corrA + psA;
            lB = lB * corrB + psB;
            #pragma unroll
            for (int nt = 0; nt < 8; nt++) {
                acc[nt][0] *= corrA; acc[nt][1] *= corrA;
                acc[nt][2] *= corrB; acc[nt][3] *= corrB;
            }
        }
        __syncwarp();   // Ps rows are warp-private

        // ---- acc += P @ V ----
        #pragma unroll
        for (int ks = 0; ks < 8; ks++) {
            int kk = ks * 8 + 2 * c;
            unsigned a[4];
            uint2 lo = *(const uint2*)&Ps[(wrow + g)     * ALD + kk];
            uint2 hi = *(const uint2*)&Ps[(wrow + g + 8) * ALD + kk];
            a[0] = lo.x; a[1] = hi.x; a[2] = lo.y; a[3] = hi.y;
            #pragma unroll
            for (int nt = 0; nt < 8; nt++) {
                uint2 b = *(const uint2*)&Vt[(nt * 8 + g) * ALD + kk];
                mma_tf32(acc[nt], a, b.x, b.y);
            }
        }
    }

    // epilogue
    {
        int rA = row0 + wrow + g;
        int rB = rA + 8;
        float invA = 1.0f / lA;
        float invB = 1.0f / lB;
        #pragma unroll
        for (int nt = 0; nt < 8; nt++) {
            int col = h * E_ + nt * 8 + 2 * c;
            *(float2*)&O[(size_t)rA * D_ + col] =
                make_float2(acc[nt][0] * invA, acc[nt][1] * invA);
            *(float2*)&O[(size_t)rB * D_ + col] =
                make_float2(acc[nt][2] * invB, acc[nt][3] * invB);
        }
    }
}

// ---------------------------------------------------------------------------
// Mean-pool over TQ=8
// ---------------------------------------------------------------------------
__global__ void pool_kernel(const float* __restrict__ O, float* __restrict__ P) {
    int idx = blockIdx.x * 256 + threadIdx.x;
    if (idx >= BLn * D_) return;
    int bl = idx / D_, d = idx % D_;
    float s = 0.f;
    #pragma unroll
    for (int tq = 0; tq < TQn; tq++)
        s += O[(size_t)(bl * TQn + tq) * D_ + d];
    P[idx] = s * (1.0f / TQn);
}

// ---------------------------------------------------------------------------
extern "C" void kernel_launch(void* const* d_in, const int* in_sizes, int n_in,
                              void* d_out, int out_size) {
    const float* target     = (const float*)d_in[0];
    const float* key_bank   = (const float*)d_in[1];
    const float* value_bank = (const float*)d_in[2];
    const int*   bank_mask  = (const int*)  d_in[3];
    const float* Wq = (const float*)d_in[4];
    const float* bq = (const float*)d_in[5];
    const float* Wk = (const float*)d_in[6];
    const float* bk = (const float*)d_in[7];
    const float* Wv = (const float*)d_in[8];
    const float* bv = (const float*)d_in[9];
    const float* Wo = (const float*)d_in[10];
    const float* bo = (const float*)d_in[11];
    const float* gq = (const float*)d_in[12];
    const float* betaq = (const float*)d_in[13];
    const float* gkv = (const float*)d_in[14];
    const float* betakv = (const float*)d_in[15];
    float* out = (float*)d_out;

    float *Xq, *Xk, *Xv, *Qb, *Kb, *Vb, *Ob, *Pool;
    cudaGetSymbolAddress((void**)&Xq,  g_Xq);
    cudaGetSymbolAddress((void**)&Xk,  g_Xk);
    cudaGetSymbolAddress((void**)&Xv,  g_Xv);
    cudaGetSymbolAddress((void**)&Qb,  g_Qb);
    cudaGetSymbolAddress((void**)&Kb,  g_Kb);
    cudaGetSymbolAddress((void**)&Vb,  g_Vb);
    cudaGetSymbolAddress((void**)&Ob,  g_Ob);
    cudaGetSymbolAddress((void**)&Pool, g_Pool);

    cudaFuncSetAttribute(attn_tf32,
                         cudaFuncAttributeMaxDynamicSharedMemorySize, ATTN_SMEM);

    // 1. LayerNorms
    ln_kernel<<<MQ, 256>>>(target, Xq, gq, betaq);
    ln_kernel<<<S_, 256>>>(key_bank, Xk, gkv, betakv);
    ln_kernel<<<S_, 256>>>(value_bank, Xv, gkv, betakv);

    // 2. Q/K/V projections in one batched launch (288 CTAs)
    gemm3_tf32<<<dim3(D_ / 128, 16, 3), 256>>>(
        Xq, Wq, bq, Qb, MQ,
        Xk, Wk, bk, Kb, S_,
        Xv, Wv, bv, Vb, S_);

    // 3. Attention: 192 CTAs, occ 2 => one wave
    attn_tf32<<<dim3(MQ / AQT, H_), 256, ATTN_SMEM>>>(Qb, Kb, Vb, bank_mask, Ob);

    // 4. Mean-pool over TQ
    pool_kernel<<<(BLn * D_ + 255) / 256, 256>>>(Ob, Pool);

    // 5. Output projection
    gemm3_tf32<<<dim3(D_ / 128, 2, 1), 256>>>(
        Pool, Wo, bo, out, BLn,
        Pool, Wo, bo, out, BLn,
        Pool, Wo, bo, out, BLn);
}

// round 4
// speedup vs baseline: 1.2207x; 1.2207x over previous
#include <cuda_runtime.h>
#include <math.h>

// Problem constants
#define D_  768
#define H_  12
#define E_  64
#define S_  2000
#define MQ  2048    // B*L*TQ
#define BLn 256     // B*L
#define TQn 8

// Scratch (device globals: allocation-free)
__device__ float g_Xq[MQ * D_];
__device__ float g_Xk[S_ * D_];
__device__ float g_Xv[S_ * D_];
__device__ float g_Qb[MQ * D_];
__device__ float g_Kb[S_ * D_];
__device__ float g_Vb[S_ * D_];
__device__ float g_Ob[MQ * D_];
__device__ float g_Pool[BLn * D_];

// ---------------------------------------------------------------------------
// helpers
// ---------------------------------------------------------------------------
__device__ __forceinline__ unsigned f2tf(float x) {
    unsigned r;
    asm("cvt.rna.tf32.f32 %0, %1;" : "=r"(r) : "f"(x));
    return r;
}

__device__ __forceinline__ void mma_tf32(float* d, const unsigned* a,
                                         unsigned b0, unsigned b1) {
    asm volatile(
        "mma.sync.aligned.m16n8k8.row.col.f32.tf32.tf32.f32 "
        "{%0,%1,%2,%3},{%4,%5,%6,%7},{%8,%9},{%0,%1,%2,%3};\n"
        : "+f"(d[0]), "+f"(d[1]), "+f"(d[2]), "+f"(d[3])
        : "r"(a[0]), "r"(a[1]), "r"(a[2]), "r"(a[3]), "r"(b0), "r"(b1));
}

// ---------------------------------------------------------------------------
// LayerNorm: one block per row of 768, 256 threads
// ---------------------------------------------------------------------------
__global__ void ln_kernel(const float* __restrict__ x, float* __restrict__ y,
                          const float* __restrict__ g, const float* __restrict__ b) {
    int row = blockIdx.x;
    const float* xr = x + (size_t)row * D_;
    int t = threadIdx.x;
    float v0 = xr[t], v1 = xr[t + 256], v2 = xr[t + 512];
    float s  = v0 + v1 + v2;
    float ss = v0 * v0 + v1 * v1 + v2 * v2;

    __shared__ float redS[8], redQ[8];
    #pragma unroll
    for (int o = 16; o > 0; o >>= 1) {
        s  += __shfl_xor_sync(0xffffffffu, s, o);
        ss += __shfl_xor_sync(0xffffffffu, ss, o);
    }
    int warp = t >> 5, lane = t & 31;
    if (lane == 0) { redS[warp] = s; redQ[warp] = ss; }
    __syncthreads();
    float sum = 0.f, sq = 0.f;
    #pragma unroll
    for (int w = 0; w < 8; w++) { sum += redS[w]; sq += redQ[w]; }

    float mean = sum * (1.0f / D_);
    float var  = sq * (1.0f / D_) - mean * mean;
    float rs   = rsqrtf(var + 1e-5f);

    float* yr = y + (size_t)row * D_;
    yr[t]       = (v0 - mean) * rs * g[t]       + b[t];
    yr[t + 256] = (v1 - mean) * rs * g[t + 256] + b[t + 256];
    yr[t + 512] = (v2 - mean) * rs * g[t + 512] + b[t + 512];
}

// ---------------------------------------------------------------------------
// Batched TF32 GEMM (R2 version, verbatim): C[M][768] = A[M][768] @ W^T + bias
// CTA 128x128 tile, BK=32, 256 threads (8 warps 2x4), warp tile 64x32
// ---------------------------------------------------------------------------
__global__ __launch_bounds__(256, 2)
void gemm3_tf32(const float* A0, const float* W0, const float* bi0, float* C0, int M0,
                const float* A1, const float* W1, const float* bi1, float* C1, int M1,
                const float* A2, const float* W2, const float* bi2, float* C2, int M2) {
    const float* A; const float* W; const float* bias; float* C; int M;
    if (blockIdx.z == 0) { A = A0; W = W0; bias = bi0; C = C0; M = M0; }
    else if (blockIdx.z == 1) { A = A1; W = W1; bias = bi1; C = C1; M = M1; }
    else { A = A2; W = W2; bias = bi2; C = C2; M = M2; }

    __shared__ unsigned As[128 * 36];
    __shared__ unsigned Ws[128 * 36];

    int t = threadIdx.x, w = t >> 5, lane = t & 31;
    int g = lane >> 2, c = lane & 3;
    int wm = w >> 2, wn = w & 3;          // wm 0..1, wn 0..3
    int row0 = blockIdx.y * 128;
    int col0 = blockIdx.x * 128;

    float acc[4][4][4];
    #pragma unroll
    for (int i = 0; i < 4; i++)
        #pragma unroll
        for (int j = 0; j < 4; j++)
            #pragma unroll
            for (int k = 0; k < 4; k++) acc[i][j][k] = 0.f;

    for (int k0 = 0; k0 < D_; k0 += 32) {
        __syncthreads();
        #pragma unroll
        for (int i = t; i < 1024; i += 256) {
            int r = i >> 3, kq = (i & 7) << 2;
            int ar = row0 + r;
            float4 av = make_float4(0.f, 0.f, 0.f, 0.f);
            if (ar < M) av = *(const float4*)(A + (size_t)ar * D_ + k0 + kq);
            uint4 ua = make_uint4(f2tf(av.x), f2tf(av.y), f2tf(av.z), f2tf(av.w));
            *(uint4*)&As[r * 36 + kq] = ua;

            float4 wv = *(const float4*)(W + (size_t)(col0 + r) * D_ + k0 + kq);
            uint4 uw = make_uint4(f2tf(wv.x), f2tf(wv.y), f2tf(wv.z), f2tf(wv.w));
            *(uint4*)&Ws[r * 36 + kq] = uw;
        }
        __syncthreads();

        #pragma unroll
        for (int ks = 0; ks < 4; ks++) {
            int kk = ks * 8;
            unsigned a[4][4];
            #pragma unroll
            for (int mt = 0; mt < 4; mt++) {
                int base = wm * 64 + mt * 16;
                a[mt][0] = As[(base + g)     * 36 + kk + c];
                a[mt][1] = As[(base + g + 8) * 36 + kk + c];
                a[mt][2] = As[(base + g)     * 36 + kk + 4 + c];
                a[mt][3] = As[(base + g + 8) * 36 + kk + 4 + c];
            }
            #pragma unroll
            for (int nt = 0; nt < 4; nt++) {
                int n = wn * 32 + nt * 8 + g;
                unsigned b0 = Ws[n * 36 + kk + c];
                unsigned b1 = Ws[n * 36 + kk + 4 + c];
                #pragma unroll
                for (int mt = 0; mt < 4; mt++)
                    mma_tf32(acc[mt][nt], a[mt], b0, b1);
            }
        }
    }

    #pragma unroll
    for (int mt = 0; mt < 4; mt++) {
        int rA = row0 + wm * 64 + mt * 16 + g;
        int rB = rA + 8;
        #pragma unroll
        for (int nt = 0; nt < 4; nt++) {
            int colb = col0 + wn * 32 + nt * 8 + 2 * c;
            float b0v = bias[colb], b1v = bias[colb + 1];
            if (rA < M) {
                C[(size_t)rA * D_ + colb]     = acc[mt][nt][0] + b0v;
                C[(size_t)rA * D_ + colb + 1] = acc[mt][nt][1] + b1v;
            }
            if (rB < M) {
                C[(size_t)rB * D_ + colb]     = acc[mt][nt][2] + b0v;
                C[(size_t)rB * D_ + colb + 1] = acc[mt][nt][3] + b1v;
            }
        }
    }
}

// ---------------------------------------------------------------------------
// TF32 flash attention — R2 layouts, AQT=128 for occupancy 2.
// Per CTA: 128 query rows x head h. 8 warps, each warp owns 16 rows (one m16
// tile). SC=64 bank chunk, online softmax, quad-local reductions only.
// grid: (MQ/128, 12) = 192 CTAs, 256 threads, smem 105.7 KB, occ 2.
// ---------------------------------------------------------------------------
#define AQT 128
#define ASC 64
// smem words: Qs 128*68 + Ks 64*68 + Vs 64*72 + Ps 128*68 + mask 64
#define ATTN_WORDS (AQT*68 + ASC*68 + ASC*72 + AQT*68 + ASC)
#define ATTN_SMEM  (ATTN_WORDS * 4)

__global__ __launch_bounds__(256, 2)
void attn_tf32(const float* __restrict__ Q, const float* __restrict__ K,
               const float* __restrict__ V, const int* __restrict__ mask,
               float* __restrict__ O) {
    extern __shared__ unsigned smu[];
    unsigned* Qs = smu;                      // [128][68]
    unsigned* Ks = Qs + AQT * 68;            // [64][68]  (s-major [s][e])
    unsigned* Vs = Ks + ASC * 68;            // [64][72]  (s-major [s][e])
    unsigned* Ps = Vs + ASC * 72;            // [128][68]
    float* maskAdd = (float*)(Ps + AQT * 68);// [64]

    int h = blockIdx.y;
    int row0 = blockIdx.x * AQT;
    int t = threadIdx.x, w = t >> 5, lane = t & 31;
    int g = lane >> 2, c = lane & 3;
    int wrow = w * 16;

    // load Q tile (tf32)
    #pragma unroll 2
    for (int i = t; i < AQT * 16; i += 256) {
        int r = i >> 4, e4 = (i & 15) << 2;
        float4 q4 = *(const float4*)(Q + (size_t)(row0 + r) * D_ + h * E_ + e4);
        uint4 u = make_uint4(f2tf(q4.x), f2tf(q4.y), f2tf(q4.z), f2tf(q4.w));
        *(uint4*)&Qs[r * 68 + e4] = u;
    }

    float mA = -1e30f, mB = -1e30f, lA = 0.f, lB = 0.f;
    float acc[8][4];
    #pragma unroll
    for (int nt = 0; nt < 8; nt++)
        #pragma unroll
        for (int k = 0; k < 4; k++) acc[nt][k] = 0.f;

    const int nChunks = (S_ + ASC - 1) / ASC;   // 32
    for (int ch = 0; ch < nChunks; ch++) {
        int s0 = ch * ASC;
        __syncthreads();

        // stage K, V chunk (tf32), zero-padded tail
        #pragma unroll 2
        for (int i = t; i < ASC * 16; i += 256) {
            int s = i >> 4, e4 = (i & 15) << 2;
            int gs = s0 + s;
            float4 kv = make_float4(0.f, 0.f, 0.f, 0.f);
            float4 vv = make_float4(0.f, 0.f, 0.f, 0.f);
            if (gs < S_) {
                kv = *(const float4*)(K + (size_t)gs * D_ + h * E_ + e4);
                vv = *(const float4*)(V + (size_t)gs * D_ + h * E_ + e4);
            }
            *(uint4*)&Ks[s * 68 + e4] = make_uint4(f2tf(kv.x), f2tf(kv.y), f2tf(kv.z), f2tf(kv.w));
            *(uint4*)&Vs[s * 72 + e4] = make_uint4(f2tf(vv.x), f2tf(vv.y), f2tf(vv.z), f2tf(vv.w));
        }
        if (t < ASC) {
            int gs = s0 + t;
            maskAdd[t] = (gs < S_ && mask[gs] != 0) ? 0.f : -1e30f;
        }
        __syncthreads();

        // ---- scores = Q @ K^T ----
        float sc[8][4];
        #pragma unroll
        for (int nt = 0; nt < 8; nt++)
            #pragma unroll
            for (int k = 0; k < 4; k++) sc[nt][k] = 0.f;

        #pragma unroll
        for (int ks = 0; ks < 8; ks++) {
            int k0 = ks * 8;
            unsigned a[4];
            a[0] = Qs[(wrow + g)     * 68 + k0 + c];
            a[1] = Qs[(wrow + g + 8) * 68 + k0 + c];
            a[2] = Qs[(wrow + g)     * 68 + k0 + 4 + c];
            a[3] = Qs[(wrow + g + 8) * 68 + k0 + 4 + c];
            #pragma unroll
            for (int nt = 0; nt < 8; nt++) {
                int n0 = nt * 8;
                unsigned b0 = Ks[(n0 + g) * 68 + k0 + c];
                unsigned b1 = Ks[(n0 + g) * 68 + k0 + 4 + c];
                mma_tf32(sc[nt], a, b0, b1);
            }
        }

        // ---- online softmax (rows g and g+8 within quad) ----
        {
            float mxA = -1e30f, mxB = -1e30f;
            #pragma unroll
            for (int nt = 0; nt < 8; nt++) {
                int j0 = nt * 8 + 2 * c;
                float ma0 = maskAdd[j0], ma1 = maskAdd[j0 + 1];
                sc[nt][0] = sc[nt][0] * 0.125f + ma0;
                sc[nt][1] = sc[nt][1] * 0.125f + ma1;
                sc[nt][2] = sc[nt][2] * 0.125f + ma0;
                sc[nt][3] = sc[nt][3] * 0.125f + ma1;
                mxA = fmaxf(mxA, fmaxf(sc[nt][0], sc[nt][1]));
                mxB = fmaxf(mxB, fmaxf(sc[nt][2], sc[nt][3]));
            }
            mxA = fmaxf(mxA, __shfl_xor_sync(0xffffffffu, mxA, 1));
            mxA = fmaxf(mxA, __shfl_xor_sync(0xffffffffu, mxA, 2));
            mxB = fmaxf(mxB, __shfl_xor_sync(0xffffffffu, mxB, 1));
            mxB = fmaxf(mxB, __shfl_xor_sync(0xffffffffu, mxB, 2));

            float mnA = fmaxf(mA, mxA);
            float mnB = fmaxf(mB, mxB);
            float corrA = __expf(mA - mnA);
            float corrB = __expf(mB - mnB);
            mA = mnA; mB = mnB;

            int rowA = wrow + g, rowB = rowA + 8;
            float psA = 0.f, psB = 0.f;
            #pragma unroll
            for (int nt = 0; nt < 8; nt++) {
                float p0 = __expf(sc[nt][0] - mnA);
                float p1 = __expf(sc[nt][1] - mnA);
                float p2 = __expf(sc[nt][2] - mnB);
                float p3 = __expf(sc[nt][3] - mnB);
                psA += p0 + p1; psB += p2 + p3;
                *(uint2*)&Ps[rowA * 68 + nt * 8 + 2 * c] = make_uint2(f2tf(p0), f2tf(p1));
                *(uint2*)&Ps[rowB * 68 + nt * 8 + 2 * c] = make_uint2(f2tf(p2), f2tf(p3));
            }
            psA += __shfl_xor_sync(0xffffffffu, psA, 1);
            psA += __shfl_xor_sync(0xffffffffu, psA, 2);
            psB += __shfl_xor_sync(0xffffffffu, psB, 1);
            psB += __shfl_xor_sync(0xffffffffu, psB, 2);
            lA = lA * corrA + psA;
            lB = lB * corrB + psB;
            #pragma unroll
            for (int nt = 0; nt < 8; nt++) {
                acc[nt][0] *= corrA; acc[nt][1] *= corrA;
                acc[nt][2] *= corrB; acc[nt][3] *= corrB;
            }
        }
        __syncwarp();   // Ps rows are warp-private

        // ---- acc += P @ V ----
        #pragma unroll
        for (int ks = 0; ks < 8; ks++) {
            int k0 = ks * 8;
            unsigned a[4];
            a[0] = Ps[(wrow + g)     * 68 + k0 + c];
            a[1] = Ps[(wrow + g + 8) * 68 + k0 + c];
            a[2] = Ps[(wrow + g)     * 68 + k0 + 4 + c];
            a[3] = Ps[(wrow + g + 8) * 68 + k0 + 4 + c];
            #pragma unroll
            for (int nt = 0; nt < 8; nt++) {
                int e0 = nt * 8;
                unsigned b0 = Vs[(k0 + c)     * 72 + e0 + g];
                unsigned b1 = Vs[(k0 + 4 + c) * 72 + e0 + g];
                mma_tf32(acc[nt], a, b0, b1);
            }
        }
    }

    // epilogue
    {
        int rA = row0 + wrow + g;
        int rB = rA + 8;
        float invA = 1.0f / lA;
        float invB = 1.0f / lB;
        #pragma unroll
        for (int nt = 0; nt < 8; nt++) {
            int col = h * E_ + nt * 8 + 2 * c;
            *(float2*)&O[(size_t)rA * D_ + col] =
                make_float2(acc[nt][0] * invA, acc[nt][1] * invA);
            *(float2*)&O[(size_t)rB * D_ + col] =
                make_float2(acc[nt][2] * invB, acc[nt][3] * invB);
        }
    }
}

// ---------------------------------------------------------------------------
// Mean-pool over TQ=8
// ---------------------------------------------------------------------------
__global__ void pool_kernel(const float* __restrict__ O, float* __restrict__ P) {
    int idx = blockIdx.x * 256 + threadIdx.x;
    if (idx >= BLn * D_) return;
    int bl = idx / D_, d = idx % D_;
    float s = 0.f;
    #pragma unroll
    for (int tq = 0; tq < TQn; tq++)
        s += O[(size_t)(bl * TQn + tq) * D_ + d];
    P[idx] = s * (1.0f / TQn);
}

// ---------------------------------------------------------------------------
extern "C" void kernel_launch(void* const* d_in, const int* in_sizes, int n_in,
                              void* d_out, int out_size) {
    const float* target     = (const float*)d_in[0];
    const float* key_bank   = (const float*)d_in[1];
    const float* value_bank = (const float*)d_in[2];
    const int*   bank_mask  = (const int*)  d_in[3];
    const float* Wq = (const float*)d_in[4];
    const float* bq = (const float*)d_in[5];
    const float* Wk = (const float*)d_in[6];
    const float* bk = (const float*)d_in[7];
    const float* Wv = (const float*)d_in[8];
    const float* bv = (const float*)d_in[9];
    const float* Wo = (const float*)d_in[10];
    const float* bo = (const float*)d_in[11];
    const float* gq = (const float*)d_in[12];
    const float* betaq = (const float*)d_in[13];
    const float* gkv = (const float*)d_in[14];
    const float* betakv = (const float*)d_in[15];
    float* out = (float*)d_out;

    float *Xq, *Xk, *Xv, *Qb, *Kb, *Vb, *Ob, *Pool;
    cudaGetSymbolAddress((void**)&Xq,  g_Xq);
    cudaGetSymbolAddress((void**)&Xk,  g_Xk);
    cudaGetSymbolAddress((void**)&Xv,  g_Xv);
    cudaGetSymbolAddress((void**)&Qb,  g_Qb);
    cudaGetSymbolAddress((void**)&Kb,  g_Kb);
    cudaGetSymbolAddress((void**)&Vb,  g_Vb);
    cudaGetSymbolAddress((void**)&Ob,  g_Ob);
    cudaGetSymbolAddress((void**)&Pool, g_Pool);

    cudaFuncSetAttribute(attn_tf32,
                         cudaFuncAttributeMaxDynamicSharedMemorySize, ATTN_SMEM);

    // 1. LayerNorms
    ln_kernel<<<MQ, 256>>>(target, Xq, gq, betaq);
    ln_kernel<<<S_, 256>>>(key_bank, Xk, gkv, betakv);
    ln_kernel<<<S_, 256>>>(value_bank, Xv, gkv, betakv);

    // 2. Q/K/V projections in one batched launch (288 CTAs)
    gemm3_tf32<<<dim3(D_ / 128, 16, 3), 256>>>(
        Xq, Wq, bq, Qb, MQ,
        Xk, Wk, bk, Kb, S_,
        Xv, Wv, bv, Vb, S_);

    // 3. Attention: 192 CTAs at occ 2 => one full wave
    attn_tf32<<<dim3(MQ / AQT, H_), 256, ATTN_SMEM>>>(Qb, Kb, Vb, bank_mask, Ob);

    // 4. Mean-pool over TQ
    pool_kernel<<<(BLn * D_ + 255) / 256, 256>>>(Ob, Pool);

    // 5. Output projection
    gemm3_tf32<<<dim3(D_ / 128, 2, 1), 256>>>(
        Pool, Wo, bo, out, BLn,
        Pool, Wo, bo, out, BLn,
        Pool, Wo, bo, out, BLn);
}

// round 5
// speedup vs baseline: 1.5414x; 1.2628x over previous
#include <cuda_runtime.h>
#include <math.h>

// Problem constants
#define D_  768
#define H_  12
#define E_  64
#define S_  2000
#define MQ  2048    // B*L*TQ
#define BLn 256     // B*L
#define TQn 8
#define NSPLIT 3

// Scratch (device globals: allocation-free)
__device__ float g_Xq[MQ * D_];
__device__ float g_Xk[S_ * D_];
__device__ float g_Xv[S_ * D_];
__device__ float g_Qb[MQ * D_];
__device__ float g_Kb[S_ * D_];
__device__ float g_Vb[S_ * D_];
__device__ float g_Oacc[NSPLIT * MQ * D_];      // unnormalized per-split attn out
__device__ float g_ML[NSPLIT * MQ * H_ * 2];    // per-split (m, l)
__device__ float g_Pool[BLn * D_];

// ---------------------------------------------------------------------------
// helpers
// ---------------------------------------------------------------------------
__device__ __forceinline__ unsigned f2tf(float x) {
    unsigned r;
    asm("cvt.rna.tf32.f32 %0, %1;" : "=r"(r) : "f"(x));
    return r;
}

__device__ __forceinline__ void mma_tf32(float* d, const unsigned* a,
                                         unsigned b0, unsigned b1) {
    asm volatile(
        "mma.sync.aligned.m16n8k8.row.col.f32.tf32.tf32.f32 "
        "{%0,%1,%2,%3},{%4,%5,%6,%7},{%8,%9},{%0,%1,%2,%3};\n"
        : "+f"(d[0]), "+f"(d[1]), "+f"(d[2]), "+f"(d[3])
        : "r"(a[0]), "r"(a[1]), "r"(a[2]), "r"(a[3]), "r"(b0), "r"(b1));
}

// ---------------------------------------------------------------------------
// LayerNorm: one block per row of 768, 256 threads
// ---------------------------------------------------------------------------
__global__ void ln_kernel(const float* __restrict__ x, float* __restrict__ y,
                          const float* __restrict__ g, const float* __restrict__ b) {
    int row = blockIdx.x;
    const float* xr = x + (size_t)row * D_;
    int t = threadIdx.x;
    float v0 = xr[t], v1 = xr[t + 256], v2 = xr[t + 512];
    float s  = v0 + v1 + v2;
    float ss = v0 * v0 + v1 * v1 + v2 * v2;

    __shared__ float redS[8], redQ[8];
    #pragma unroll
    for (int o = 16; o > 0; o >>= 1) {
        s  += __shfl_xor_sync(0xffffffffu, s, o);
        ss += __shfl_xor_sync(0xffffffffu, ss, o);
    }
    int warp = t >> 5, lane = t & 31;
    if (lane == 0) { redS[warp] = s; redQ[warp] = ss; }
    __syncthreads();
    float sum = 0.f, sq = 0.f;
    #pragma unroll
    for (int w = 0; w < 8; w++) { sum += redS[w]; sq += redQ[w]; }

    float mean = sum * (1.0f / D_);
    float var  = sq * (1.0f / D_) - mean * mean;
    float rs   = rsqrtf(var + 1e-5f);

    float* yr = y + (size_t)row * D_;
    yr[t]       = (v0 - mean) * rs * g[t]       + b[t];
    yr[t + 256] = (v1 - mean) * rs * g[t + 256] + b[t + 256];
    yr[t + 512] = (v2 - mean) * rs * g[t + 512] + b[t + 512];
}

// ---------------------------------------------------------------------------
// Batched TF32 GEMM (R2 version, verbatim)
// ---------------------------------------------------------------------------
__global__ __launch_bounds__(256, 2)
void gemm3_tf32(const float* A0, const float* W0, const float* bi0, float* C0, int M0,
                const float* A1, const float* W1, const float* bi1, float* C1, int M1,
                const float* A2, const float* W2, const float* bi2, float* C2, int M2) {
    const float* A; const float* W; const float* bias; float* C; int M;
    if (blockIdx.z == 0) { A = A0; W = W0; bias = bi0; C = C0; M = M0; }
    else if (blockIdx.z == 1) { A = A1; W = W1; bias = bi1; C = C1; M = M1; }
    else { A = A2; W = W2; bias = bi2; C = C2; M = M2; }

    __shared__ unsigned As[128 * 36];
    __shared__ unsigned Ws[128 * 36];

    int t = threadIdx.x, w = t >> 5, lane = t & 31;
    int g = lane >> 2, c = lane & 3;
    int wm = w >> 2, wn = w & 3;
    int row0 = blockIdx.y * 128;
    int col0 = blockIdx.x * 128;

    float acc[4][4][4];
    #pragma unroll
    for (int i = 0; i < 4; i++)
        #pragma unroll
        for (int j = 0; j < 4; j++)
            #pragma unroll
            for (int k = 0; k < 4; k++) acc[i][j][k] = 0.f;

    for (int k0 = 0; k0 < D_; k0 += 32) {
        __syncthreads();
        #pragma unroll
        for (int i = t; i < 1024; i += 256) {
            int r = i >> 3, kq = (i & 7) << 2;
            int ar = row0 + r;
            float4 av = make_float4(0.f, 0.f, 0.f, 0.f);
            if (ar < M) av = *(const float4*)(A + (size_t)ar * D_ + k0 + kq);
            uint4 ua = make_uint4(f2tf(av.x), f2tf(av.y), f2tf(av.z), f2tf(av.w));
            *(uint4*)&As[r * 36 + kq] = ua;

            float4 wv = *(const float4*)(W + (size_t)(col0 + r) * D_ + k0 + kq);
            uint4 uw = make_uint4(f2tf(wv.x), f2tf(wv.y), f2tf(wv.z), f2tf(wv.w));
            *(uint4*)&Ws[r * 36 + kq] = uw;
        }
        __syncthreads();

        #pragma unroll
        for (int ks = 0; ks < 4; ks++) {
            int kk = ks * 8;
            unsigned a[4][4];
            #pragma unroll
            for (int mt = 0; mt < 4; mt++) {
                int base = wm * 64 + mt * 16;
                a[mt][0] = As[(base + g)     * 36 + kk + c];
                a[mt][1] = As[(base + g + 8) * 36 + kk + c];
                a[mt][2] = As[(base + g)     * 36 + kk + 4 + c];
                a[mt][3] = As[(base + g + 8) * 36 + kk + 4 + c];
            }
            #pragma unroll
            for (int nt = 0; nt < 4; nt++) {
                int n = wn * 32 + nt * 8 + g;
                unsigned b0 = Ws[n * 36 + kk + c];
                unsigned b1 = Ws[n * 36 + kk + 4 + c];
                #pragma unroll
                for (int mt = 0; mt < 4; mt++)
                    mma_tf32(acc[mt][nt], a[mt], b0, b1);
            }
        }
    }

    #pragma unroll
    for (int mt = 0; mt < 4; mt++) {
        int rA = row0 + wm * 64 + mt * 16 + g;
        int rB = rA + 8;
        #pragma unroll
        for (int nt = 0; nt < 4; nt++) {
            int colb = col0 + wn * 32 + nt * 8 + 2 * c;
            float b0v = bias[colb], b1v = bias[colb + 1];
            if (rA < M) {
                C[(size_t)rA * D_ + colb]     = acc[mt][nt][0] + b0v;
                C[(size_t)rA * D_ + colb + 1] = acc[mt][nt][1] + b1v;
            }
            if (rB < M) {
                C[(size_t)rB * D_ + colb]     = acc[mt][nt][2] + b0v;
                C[(size_t)rB * D_ + colb + 1] = acc[mt][nt][3] + b1v;
            }
        }
    }
}

// ---------------------------------------------------------------------------
// TF32 flash attention — R2 mainloop verbatim, split-KV over blockIdx.z.
// Per CTA: 256 query rows x head h x 1/3 of bank chunks.
// Epilogue stores UNNORMALIZED acc + (m, l) per row.
// grid: (MQ/256, 12, 3) = 288 CTAs, 256 threads.
// ---------------------------------------------------------------------------
#define AQT 256
#define ASC 64
#define NCH ((S_ + ASC - 1) / ASC)              /* 32 */
#define CHSPLIT ((NCH + NSPLIT - 1) / NSPLIT)   /* 11 */
#define ATTN_WORDS (256*68 + 64*68 + 64*72 + 256*68 + 64)
#define ATTN_SMEM  (ATTN_WORDS * 4)

__global__ __launch_bounds__(256, 1)
void attn_tf32(const float* __restrict__ Q, const float* __restrict__ K,
               const float* __restrict__ V, const int* __restrict__ mask,
               float* __restrict__ Oacc, float* __restrict__ ML) {
    extern __shared__ unsigned smu[];
    unsigned* Qs = smu;                      // [256][68]
    unsigned* Ks = Qs + 256 * 68;            // [64][68]
    unsigned* Vs = Ks + 64 * 68;             // [64][72]
    unsigned* Ps = Vs + 64 * 72;             // [256][68]
    float* maskAdd = (float*)(Ps + 256 * 68);// [64]

    int h = blockIdx.y;
    int z = blockIdx.z;
    int row0 = blockIdx.x * AQT;
    int t = threadIdx.x, w = t >> 5, lane = t & 31;
    int g = lane >> 2, c = lane & 3;
    int wrow = w * 32;

    // load Q tile (tf32)
    #pragma unroll 4
    for (int i = t; i < AQT * 16; i += 256) {
        int r = i >> 4, e4 = (i & 15) << 2;
        float4 q4 = *(const float4*)(Q + (size_t)(row0 + r) * D_ + h * E_ + e4);
        uint4 u = make_uint4(f2tf(q4.x), f2tf(q4.y), f2tf(q4.z), f2tf(q4.w));
        *(uint4*)&Qs[r * 68 + e4] = u;
    }

    float mA[2] = {-1e30f, -1e30f}, mB[2] = {-1e30f, -1e30f};
    float lA[2] = {0.f, 0.f}, lB[2] = {0.f, 0.f};
    float acc[2][8][4];
    #pragma unroll
    for (int mt = 0; mt < 2; mt++)
        #pragma unroll
        for (int nt = 0; nt < 8; nt++)
            #pragma unroll
            for (int k = 0; k < 4; k++) acc[mt][nt][k] = 0.f;

    int chBeg = z * CHSPLIT;
    int chEnd = min(chBeg + CHSPLIT, NCH);
    for (int ch = chBeg; ch < chEnd; ch++) {
        int s0 = ch * ASC;
        __syncthreads();

        // stage K, V chunk (tf32), zero-padded tail
        #pragma unroll 4
        for (int i = t; i < ASC * 16; i += 256) {
            int s = i >> 4, e4 = (i & 15) << 2;
            int gs = s0 + s;
            float4 kv = make_float4(0.f, 0.f, 0.f, 0.f);
            float4 vv = make_float4(0.f, 0.f, 0.f, 0.f);
            if (gs < S_) {
                kv = *(const float4*)(K + (size_t)gs * D_ + h * E_ + e4);
                vv = *(const float4*)(V + (size_t)gs * D_ + h * E_ + e4);
            }
            *(uint4*)&Ks[s * 68 + e4] = make_uint4(f2tf(kv.x), f2tf(kv.y), f2tf(kv.z), f2tf(kv.w));
            *(uint4*)&Vs[s * 72 + e4] = make_uint4(f2tf(vv.x), f2tf(vv.y), f2tf(vv.z), f2tf(vv.w));
        }
        if (t < ASC) {
            int gs = s0 + t;
            maskAdd[t] = (gs < S_ && mask[gs] != 0) ? 0.f : -1e30f;
        }
        __syncthreads();

        // ---- scores = Q @ K^T ----
        float sc[2][8][4];
        #pragma unroll
        for (int mt = 0; mt < 2; mt++)
            #pragma unroll
            for (int nt = 0; nt < 8; nt++)
                #pragma unroll
                for (int k = 0; k < 4; k++) sc[mt][nt][k] = 0.f;

        #pragma unroll
        for (int ks = 0; ks < 8; ks++) {
            int k0 = ks * 8;
            unsigned a[2][4];
            #pragma unroll
            for (int mt = 0; mt < 2; mt++) {
                int base = wrow + mt * 16;
                a[mt][0] = Qs[(base + g)     * 68 + k0 + c];
                a[mt][1] = Qs[(base + g + 8) * 68 + k0 + c];
                a[mt][2] = Qs[(base + g)     * 68 + k0 + 4 + c];
                a[mt][3] = Qs[(base + g + 8) * 68 + k0 + 4 + c];
            }
            #pragma unroll
            for (int nt = 0; nt < 8; nt++) {
                int n0 = nt * 8;
                unsigned b0 = Ks[(n0 + g) * 68 + k0 + c];
                unsigned b1 = Ks[(n0 + g) * 68 + k0 + 4 + c];
                mma_tf32(sc[0][nt], a[0], b0, b1);
                mma_tf32(sc[1][nt], a[1], b0, b1);
            }
        }

        // ---- online softmax ----
        #pragma unroll
        for (int mt = 0; mt < 2; mt++) {
            float mxA = -1e30f, mxB = -1e30f;
            #pragma unroll
            for (int nt = 0; nt < 8; nt++) {
                int j0 = nt * 8 + 2 * c;
                float ma0 = maskAdd[j0], ma1 = maskAdd[j0 + 1];
                sc[mt][nt][0] = sc[mt][nt][0] * 0.125f + ma0;
                sc[mt][nt][1] = sc[mt][nt][1] * 0.125f + ma1;
                sc[mt][nt][2] = sc[mt][nt][2] * 0.125f + ma0;
                sc[mt][nt][3] = sc[mt][nt][3] * 0.125f + ma1;
                mxA = fmaxf(mxA, fmaxf(sc[mt][nt][0], sc[mt][nt][1]));
                mxB = fmaxf(mxB, fmaxf(sc[mt][nt][2], sc[mt][nt][3]));
            }
            mxA = fmaxf(mxA, __shfl_xor_sync(0xffffffffu, mxA, 1));
            mxA = fmaxf(mxA, __shfl_xor_sync(0xffffffffu, mxA, 2));
            mxB = fmaxf(mxB, __shfl_xor_sync(0xffffffffu, mxB, 1));
            mxB = fmaxf(mxB, __shfl_xor_sync(0xffffffffu, mxB, 2));

            float mnA = fmaxf(mA[mt], mxA);
            float mnB = fmaxf(mB[mt], mxB);
            float corrA = __expf(mA[mt] - mnA);
            float corrB = __expf(mB[mt] - mnB);
            mA[mt] = mnA; mB[mt] = mnB;

            int rowA = wrow + mt * 16 + g;
            int rowB = rowA + 8;
            float psA = 0.f, psB = 0.f;
            #pragma unroll
            for (int nt = 0; nt < 8; nt++) {
                float p0 = __expf(sc[mt][nt][0] - mnA);
                float p1 = __expf(sc[mt][nt][1] - mnA);
                float p2 = __expf(sc[mt][nt][2] - mnB);
                float p3 = __expf(sc[mt][nt][3] - mnB);
                psA += p0 + p1; psB += p2 + p3;
                *(uint2*)&Ps[rowA * 68 + nt * 8 + 2 * c] = make_uint2(f2tf(p0), f2tf(p1));
                *(uint2*)&Ps[rowB * 68 + nt * 8 + 2 * c] = make_uint2(f2tf(p2), f2tf(p3));
            }
            psA += __shfl_xor_sync(0xffffffffu, psA, 1);
            psA += __shfl_xor_sync(0xffffffffu, psA, 2);
            psB += __shfl_xor_sync(0xffffffffu, psB, 1);
            psB += __shfl_xor_sync(0xffffffffu, psB, 2);
            lA[mt] = lA[mt] * corrA + psA;
            lB[mt] = lB[mt] * corrB + psB;
            #pragma unroll
            for (int nt = 0; nt < 8; nt++) {
                acc[mt][nt][0] *= corrA; acc[mt][nt][1] *= corrA;
                acc[mt][nt][2] *= corrB; acc[mt][nt][3] *= corrB;
            }
        }
        __syncwarp();   // Ps rows are warp-private

        // ---- acc += P @ V ----
        #pragma unroll
        for (int ks = 0; ks < 8; ks++) {
            int k0 = ks * 8;
            unsigned a[2][4];
            #pragma unroll
            for (int mt = 0; mt < 2; mt++) {
                int base = wrow + mt * 16;
                a[mt][0] = Ps[(base + g)     * 68 + k0 + c];
                a[mt][1] = Ps[(base + g + 8) * 68 + k0 + c];
                a[mt][2] = Ps[(base + g)     * 68 + k0 + 4 + c];
                a[mt][3] = Ps[(base + g + 8) * 68 + k0 + 4 + c];
            }
            #pragma unroll
            for (int nt = 0; nt < 8; nt++) {
                int e0 = nt * 8;
                unsigned b0 = Vs[(k0 + c)     * 72 + e0 + g];
                unsigned b1 = Vs[(k0 + 4 + c) * 72 + e0 + g];
                mma_tf32(acc[0][nt], a[0], b0, b1);
                mma_tf32(acc[1][nt], a[1], b0, b1);
            }
        }
    }

    // epilogue: store unnormalized acc + (m,l)
    #pragma unroll
    for (int mt = 0; mt < 2; mt++) {
        int rA = row0 + wrow + mt * 16 + g;
        int rB = rA + 8;
        float* obase = Oacc + (size_t)z * MQ * D_;
        #pragma unroll
        for (int nt = 0; nt < 8; nt++) {
            int col = h * E_ + nt * 8 + 2 * c;
            *(float2*)&obase[(size_t)rA * D_ + col] =
                make_float2(acc[mt][nt][0], acc[mt][nt][1]);
            *(float2*)&obase[(size_t)rB * D_ + col] =
                make_float2(acc[mt][nt][2], acc[mt][nt][3]);
        }
        if (c == 0) {
            size_t iA = ((size_t)(z * MQ + rA) * H_ + h) * 2;
            size_t iB = ((size_t)(z * MQ + rB) * H_ + h) * 2;
            ML[iA]     = mA[mt]; ML[iA + 1] = lA[mt];
            ML[iB]     = mB[mt]; ML[iB + 1] = lB[mt];
        }
    }
}

// ---------------------------------------------------------------------------
// Split-KV combine + mean-pool over TQ=8: (3,2048,768) -> (256,768)
// ---------------------------------------------------------------------------
__global__ void combine_pool_kernel(const float* __restrict__ Oacc,
                                    const float* __restrict__ ML,
                                    float* __restrict__ P) {
    int idx = blockIdx.x * 256 + threadIdx.x;
    if (idx >= BLn * D_) return;
    int bl = idx / D_, d = idx % D_;
    int h = d >> 6;
    float s = 0.f;
    #pragma unroll
    for (int tq = 0; tq < TQn; tq++) {
        int row = bl * TQn + tq;
        size_t i0 = ((size_t)(0 * MQ + row) * H_ + h) * 2;
        size_t i1 = ((size_t)(1 * MQ + row) * H_ + h) * 2;
        size_t i2 = ((size_t)(2 * MQ + row) * H_ + h) * 2;
        float m0 = ML[i0], l0 = ML[i0 + 1];
        float m1 = ML[i1], l1 = ML[i1 + 1];
        float m2 = ML[i2], l2 = ML[i2 + 1];
        float M = fmaxf(m0, fmaxf(m1, m2));
        float w0 = __expf(m0 - M), w1 = __expf(m1 - M), w2 = __expf(m2 - M);
        float denom = l0 * w0 + l1 * w1 + l2 * w2;
        float a0 = Oacc[(size_t)(0 * MQ + row) * D_ + d];
        float a1 = Oacc[(size_t)(1 * MQ + row) * D_ + d];
        float a2 = Oacc[(size_t)(2 * MQ + row) * D_ + d];
        s += (a0 * w0 + a1 * w1 + a2 * w2) / denom;
    }
    P[idx] = s * (1.0f / TQn);
}

// ---------------------------------------------------------------------------
extern "C" void kernel_launch(void* const* d_in, const int* in_sizes, int n_in,
                              void* d_out, int out_size) {
    const float* target     = (const float*)d_in[0];
    const float* key_bank   = (const float*)d_in[1];
    const float* value_bank = (const float*)d_in[2];
    const int*   bank_mask  = (const int*)  d_in[3];
    const float* Wq = (const float*)d_in[4];
    const float* bq = (const float*)d_in[5];
    const float* Wk = (const float*)d_in[6];
    const float* bk = (const float*)d_in[7];
    const float* Wv = (const float*)d_in[8];
    const float* bv = (const float*)d_in[9];
    const float* Wo = (const float*)d_in[10];
    const float* bo = (const float*)d_in[11];
    const float* gq = (const float*)d_in[12];
    const float* betaq = (const float*)d_in[13];
    const float* gkv = (const float*)d_in[14];
    const float* betakv = (const float*)d_in[15];
    float* out = (float*)d_out;

    float *Xq, *Xk, *Xv, *Qb, *Kb, *Vb, *Oacc, *ML, *Pool;
    cudaGetSymbolAddress((void**)&Xq,  g_Xq);
    cudaGetSymbolAddress((void**)&Xk,  g_Xk);
    cudaGetSymbolAddress((void**)&Xv,  g_Xv);
    cudaGetSymbolAddress((void**)&Qb,  g_Qb);
    cudaGetSymbolAddress((void**)&Kb,  g_Kb);
    cudaGetSymbolAddress((void**)&Vb,  g_Vb);
    cudaGetSymbolAddress((void**)&Oacc, g_Oacc);
    cudaGetSymbolAddress((void**)&ML,  g_ML);
    cudaGetSymbolAddress((void**)&Pool, g_Pool);

    cudaFuncSetAttribute(attn_tf32,
                         cudaFuncAttributeMaxDynamicSharedMemorySize, ATTN_SMEM);

    // 1. LayerNorms
    ln_kernel<<<MQ, 256>>>(target, Xq, gq, betaq);
    ln_kernel<<<S_, 256>>>(key_bank, Xk, gkv, betakv);
    ln_kernel<<<S_, 256>>>(value_bank, Xv, gkv, betakv);

    // 2. Q/K/V projections in one batched launch (288 CTAs)
    gemm3_tf32<<<dim3(D_ / 128, 16, 3), 256>>>(
        Xq, Wq, bq, Qb, MQ,
        Xk, Wk, bk, Kb, S_,
        Xv, Wv, bv, Vb, S_);

    // 3. Attention: split-KV x3 => 288 CTAs, ~2 waves of 1/3 work each
    attn_tf32<<<dim3(MQ / AQT, H_, NSPLIT), 256, ATTN_SMEM>>>(
        Qb, Kb, Vb, bank_mask, Oacc, ML);

    // 4. Combine splits + mean-pool over TQ
    combine_pool_kernel<<<(BLn * D_ + 255) / 256, 256>>>(Oacc, ML, Pool);

    // 5. Output projection
    gemm3_tf32<<<dim3(D_ / 128, 2, 1), 256>>>(
        Pool, Wo, bo, out, BLn,
        Pool, Wo, bo, out, BLn,
        Pool, Wo, bo, out, BLn);
}

// round 6
// speedup vs baseline: 1.6613x; 1.0778x over previous
#include <cuda_runtime.h>
#include <math.h>

// Problem constants
#define D_  768
#define H_  12
#define E_  64
#define S_  2000
#define MQ  2048    // B*L*TQ
#define BLn 256     // B*L
#define TQn 8
#define NSPLIT 3

// Scratch (device globals: allocation-free)
__device__ float g_Xq[MQ * D_];
__device__ float g_Xk[S_ * D_];
__device__ float g_Xv[S_ * D_];
__device__ float g_Qb[MQ * D_];
__device__ float g_Kb[S_ * D_];
__device__ float g_Vb[S_ * D_];
__device__ float g_Oacc[NSPLIT * MQ * D_];      // unnormalized per-split attn out
__device__ float g_ML[NSPLIT * MQ * H_ * 2];    // per-split (m, l)
__device__ float g_Pool[BLn * D_];

// ---------------------------------------------------------------------------
// helpers
// ---------------------------------------------------------------------------
__device__ __forceinline__ unsigned f2tf(float x) {
    unsigned r;
    asm("cvt.rna.tf32.f32 %0, %1;" : "=r"(r) : "f"(x));
    return r;
}

__device__ __forceinline__ void mma_tf32(float* d, const unsigned* a,
                                         unsigned b0, unsigned b1) {
    asm volatile(
        "mma.sync.aligned.m16n8k8.row.col.f32.tf32.tf32.f32 "
        "{%0,%1,%2,%3},{%4,%5,%6,%7},{%8,%9},{%0,%1,%2,%3};\n"
        : "+f"(d[0]), "+f"(d[1]), "+f"(d[2]), "+f"(d[3])
        : "r"(a[0]), "r"(a[1]), "r"(a[2]), "r"(a[3]), "r"(b0), "r"(b1));
}

// ---------------------------------------------------------------------------
// LayerNorm: one block per row of 768, 256 threads
// ---------------------------------------------------------------------------
__global__ void ln_kernel(const float* __restrict__ x, float* __restrict__ y,
                          const float* __restrict__ g, const float* __restrict__ b) {
    int row = blockIdx.x;
    const float* xr = x + (size_t)row * D_;
    int t = threadIdx.x;
    float v0 = xr[t], v1 = xr[t + 256], v2 = xr[t + 512];
    float s  = v0 + v1 + v2;
    float ss = v0 * v0 + v1 * v1 + v2 * v2;

    __shared__ float redS[8], redQ[8];
    #pragma unroll
    for (int o = 16; o > 0; o >>= 1) {
        s  += __shfl_xor_sync(0xffffffffu, s, o);
        ss += __shfl_xor_sync(0xffffffffu, ss, o);
    }
    int warp = t >> 5, lane = t & 31;
    if (lane == 0) { redS[warp] = s; redQ[warp] = ss; }
    __syncthreads();
    float sum = 0.f, sq = 0.f;
    #pragma unroll
    for (int w = 0; w < 8; w++) { sum += redS[w]; sq += redQ[w]; }

    float mean = sum * (1.0f / D_);
    float var  = sq * (1.0f / D_) - mean * mean;
    float rs   = rsqrtf(var + 1e-5f);

    float* yr = y + (size_t)row * D_;
    yr[t]       = (v0 - mean) * rs * g[t]       + b[t];
    yr[t + 256] = (v1 - mean) * rs * g[t + 256] + b[t + 256];
    yr[t + 512] = (v2 - mean) * rs * g[t + 512] + b[t + 512];
}

// ---------------------------------------------------------------------------
// Batched TF32 GEMM (R2 version, verbatim)
// ---------------------------------------------------------------------------
__global__ __launch_bounds__(256, 2)
void gemm3_tf32(const float* A0, const float* W0, const float* bi0, float* C0, int M0,
                const float* A1, const float* W1, const float* bi1, float* C1, int M1,
                const float* A2, const float* W2, const float* bi2, float* C2, int M2) {
    const float* A; const float* W; const float* bias; float* C; int M;
    if (blockIdx.z == 0) { A = A0; W = W0; bias = bi0; C = C0; M = M0; }
    else if (blockIdx.z == 1) { A = A1; W = W1; bias = bi1; C = C1; M = M1; }
    else { A = A2; W = W2; bias = bi2; C = C2; M = M2; }

    __shared__ unsigned As[128 * 36];
    __shared__ unsigned Ws[128 * 36];

    int t = threadIdx.x, w = t >> 5, lane = t & 31;
    int g = lane >> 2, c = lane & 3;
    int wm = w >> 2, wn = w & 3;
    int row0 = blockIdx.y * 128;
    int col0 = blockIdx.x * 128;

    float acc[4][4][4];
    #pragma unroll
    for (int i = 0; i < 4; i++)
        #pragma unroll
        for (int j = 0; j < 4; j++)
            #pragma unroll
            for (int k = 0; k < 4; k++) acc[i][j][k] = 0.f;

    for (int k0 = 0; k0 < D_; k0 += 32) {
        __syncthreads();
        #pragma unroll
        for (int i = t; i < 1024; i += 256) {
            int r = i >> 3, kq = (i & 7) << 2;
            int ar = row0 + r;
            float4 av = make_float4(0.f, 0.f, 0.f, 0.f);
            if (ar < M) av = *(const float4*)(A + (size_t)ar * D_ + k0 + kq);
            uint4 ua = make_uint4(f2tf(av.x), f2tf(av.y), f2tf(av.z), f2tf(av.w));
            *(uint4*)&As[r * 36 + kq] = ua;

            float4 wv = *(const float4*)(W + (size_t)(col0 + r) * D_ + k0 + kq);
            uint4 uw = make_uint4(f2tf(wv.x), f2tf(wv.y), f2tf(wv.z), f2tf(wv.w));
            *(uint4*)&Ws[r * 36 + kq] = uw;
        }
        __syncthreads();

        #pragma unroll
        for (int ks = 0; ks < 4; ks++) {
            int kk = ks * 8;
            unsigned a[4][4];
            #pragma unroll
            for (int mt = 0; mt < 4; mt++) {
                int base = wm * 64 + mt * 16;
                a[mt][0] = As[(base + g)     * 36 + kk + c];
                a[mt][1] = As[(base + g + 8) * 36 + kk + c];
                a[mt][2] = As[(base + g)     * 36 + kk + 4 + c];
                a[mt][3] = As[(base + g + 8) * 36 + kk + 4 + c];
            }
            #pragma unroll
            for (int nt = 0; nt < 4; nt++) {
                int n = wn * 32 + nt * 8 + g;
                unsigned b0 = Ws[n * 36 + kk + c];
                unsigned b1 = Ws[n * 36 + kk + 4 + c];
                #pragma unroll
                for (int mt = 0; mt < 4; mt++)
                    mma_tf32(acc[mt][nt], a[mt], b0, b1);
            }
        }
    }

    #pragma unroll
    for (int mt = 0; mt < 4; mt++) {
        int rA = row0 + wm * 64 + mt * 16 + g;
        int rB = rA + 8;
        #pragma unroll
        for (int nt = 0; nt < 4; nt++) {
            int colb = col0 + wn * 32 + nt * 8 + 2 * c;
            float b0v = bias[colb], b1v = bias[colb + 1];
            if (rA < M) {
                C[(size_t)rA * D_ + colb]     = acc[mt][nt][0] + b0v;
                C[(size_t)rA * D_ + colb + 1] = acc[mt][nt][1] + b1v;
            }
            if (rB < M) {
                C[(size_t)rB * D_ + colb]     = acc[mt][nt][2] + b0v;
                C[(size_t)rB * D_ + colb + 1] = acc[mt][nt][3] + b1v;
            }
        }
    }
}

// ---------------------------------------------------------------------------
// TF32 flash attention v3: no P smem round-trip (permuted-K PV), ASC=32,
// occupancy 2, split-KV x3. Per CTA: 256 query rows x head h x 1/3 chunks.
// The PV mma consumes the exp'd score fragments DIRECTLY from registers;
// V rows are staged in the matching permuted order:
//   smem row of V row (8q+w) = 8q + (w even ? w/2 : 4+(w-1)/2)
// grid: (8, 12, 3) = 288 CTAs, 256 threads, smem 87.7 KB, occ 2 = one wave.
// ---------------------------------------------------------------------------
#define AQT 256
#define ASC 32
#define NCH ((S_ + ASC - 1) / ASC)              /* 63 */
#define CHSPLIT ((NCH + NSPLIT - 1) / NSPLIT)   /* 21 */
// smem words: Qs 256*68 + Ks 32*68 + Vs 32*72 + mask 32
#define ATTN_WORDS (AQT*68 + ASC*68 + ASC*72 + ASC)
#define ATTN_SMEM  (ATTN_WORDS * 4)

__global__ __launch_bounds__(256, 2)
void attn_tf32(const float* __restrict__ Q, const float* __restrict__ K,
               const float* __restrict__ V, const int* __restrict__ mask,
               float* __restrict__ Oacc, float* __restrict__ ML) {
    extern __shared__ unsigned smu[];
    unsigned* Qs = smu;                      // [256][68]
    unsigned* Ks = Qs + AQT * 68;            // [32][68]
    unsigned* Vs = Ks + ASC * 68;            // [32][72] rows permuted
    float* maskAdd = (float*)(Vs + ASC * 72);// [32]

    int h = blockIdx.y;
    int z = blockIdx.z;
    int row0 = blockIdx.x * AQT;
    int t = threadIdx.x, w = t >> 5, lane = t & 31;
    int g = lane >> 2, c = lane & 3;
    int wrow = w * 32;

    // load Q tile (tf32)
    #pragma unroll 4
    for (int i = t; i < AQT * 16; i += 256) {
        int r = i >> 4, e4 = (i & 15) << 2;
        float4 q4 = *(const float4*)(Q + (size_t)(row0 + r) * D_ + h * E_ + e4);
        uint4 u = make_uint4(f2tf(q4.x), f2tf(q4.y), f2tf(q4.z), f2tf(q4.w));
        *(uint4*)&Qs[r * 68 + e4] = u;
    }

    float mA[2] = {-1e30f, -1e30f}, mB[2] = {-1e30f, -1e30f};
    float lA[2] = {0.f, 0.f}, lB[2] = {0.f, 0.f};
    float acc[2][8][4];
    #pragma unroll
    for (int mt = 0; mt < 2; mt++)
        #pragma unroll
        for (int nt = 0; nt < 8; nt++)
            #pragma unroll
            for (int k = 0; k < 4; k++) acc[mt][nt][k] = 0.f;

    int chBeg = z * CHSPLIT;
    int chEnd = min(chBeg + CHSPLIT, NCH);
    for (int ch = chBeg; ch < chEnd; ch++) {
        int s0 = ch * ASC;
        __syncthreads();

        // stage K (natural rows) and V (permuted rows); zero tail
        #pragma unroll 2
        for (int i = t; i < ASC * 16; i += 256) {
            int s = i >> 4, e4 = (i & 15) << 2;
            int gs = s0 + s;
            float4 kv = make_float4(0.f, 0.f, 0.f, 0.f);
            float4 vv = make_float4(0.f, 0.f, 0.f, 0.f);
            if (gs < S_) {
                kv = *(const float4*)(K + (size_t)gs * D_ + h * E_ + e4);
                vv = *(const float4*)(V + (size_t)gs * D_ + h * E_ + e4);
            }
            *(uint4*)&Ks[s * 68 + e4] = make_uint4(f2tf(kv.x), f2tf(kv.y), f2tf(kv.z), f2tf(kv.w));
            int sw = s & 7;
            int sp = (s & ~7) | ((sw & 1) ? 4 + (sw >> 1) : (sw >> 1));
            *(uint4*)&Vs[sp * 72 + e4] = make_uint4(f2tf(vv.x), f2tf(vv.y), f2tf(vv.z), f2tf(vv.w));
        }
        if (t < ASC) {
            int gs = s0 + t;
            maskAdd[t] = (gs < S_ && mask[gs] != 0) ? 0.f : -1e30f;
        }
        __syncthreads();

        // ---- scores = Q @ K^T  (32 cols) ----
        float sc[2][4][4];
        #pragma unroll
        for (int mt = 0; mt < 2; mt++)
            #pragma unroll
            for (int nt = 0; nt < 4; nt++)
                #pragma unroll
                for (int k = 0; k < 4; k++) sc[mt][nt][k] = 0.f;

        #pragma unroll
        for (int ks = 0; ks < 8; ks++) {
            int k0 = ks * 8;
            unsigned a[2][4];
            #pragma unroll
            for (int mt = 0; mt < 2; mt++) {
                int base = wrow + mt * 16;
                a[mt][0] = Qs[(base + g)     * 68 + k0 + c];
                a[mt][1] = Qs[(base + g + 8) * 68 + k0 + c];
                a[mt][2] = Qs[(base + g)     * 68 + k0 + 4 + c];
                a[mt][3] = Qs[(base + g + 8) * 68 + k0 + 4 + c];
            }
            #pragma unroll
            for (int nt = 0; nt < 4; nt++) {
                int n0 = nt * 8;
                unsigned b0 = Ks[(n0 + g) * 68 + k0 + c];
                unsigned b1 = Ks[(n0 + g) * 68 + k0 + 4 + c];
                mma_tf32(sc[0][nt], a[0], b0, b1);
                mma_tf32(sc[1][nt], a[1], b0, b1);
            }
        }

        // ---- online softmax; exp'd P stays in sc (as tf32 bit patterns) ----
        #pragma unroll
        for (int mt = 0; mt < 2; mt++) {
            float mxA = -1e30f, mxB = -1e30f;
            #pragma unroll
            for (int nt = 0; nt < 4; nt++) {
                int j0 = nt * 8 + 2 * c;
                float ma0 = maskAdd[j0], ma1 = maskAdd[j0 + 1];
                sc[mt][nt][0] = sc[mt][nt][0] * 0.125f + ma0;
                sc[mt][nt][1] = sc[mt][nt][1] * 0.125f + ma1;
                sc[mt][nt][2] = sc[mt][nt][2] * 0.125f + ma0;
                sc[mt][nt][3] = sc[mt][nt][3] * 0.125f + ma1;
                mxA = fmaxf(mxA, fmaxf(sc[mt][nt][0], sc[mt][nt][1]));
                mxB = fmaxf(mxB, fmaxf(sc[mt][nt][2], sc[mt][nt][3]));
            }
            mxA = fmaxf(mxA, __shfl_xor_sync(0xffffffffu, mxA, 1));
            mxA = fmaxf(mxA, __shfl_xor_sync(0xffffffffu, mxA, 2));
            mxB = fmaxf(mxB, __shfl_xor_sync(0xffffffffu, mxB, 1));
            mxB = fmaxf(mxB, __shfl_xor_sync(0xffffffffu, mxB, 2));

            float mnA = fmaxf(mA[mt], mxA);
            float mnB = fmaxf(mB[mt], mxB);
            float corrA = __expf(mA[mt] - mnA);
            float corrB = __expf(mB[mt] - mnB);
            mA[mt] = mnA; mB[mt] = mnB;

            float psA = 0.f, psB = 0.f;
            #pragma unroll
            for (int nt = 0; nt < 4; nt++) {
                float p0 = __expf(sc[mt][nt][0] - mnA);
                float p1 = __expf(sc[mt][nt][1] - mnA);
                float p2 = __expf(sc[mt][nt][2] - mnB);
                float p3 = __expf(sc[mt][nt][3] - mnB);
                psA += p0 + p1; psB += p2 + p3;
                sc[mt][nt][0] = __uint_as_float(f2tf(p0));
                sc[mt][nt][1] = __uint_as_float(f2tf(p1));
                sc[mt][nt][2] = __uint_as_float(f2tf(p2));
                sc[mt][nt][3] = __uint_as_float(f2tf(p3));
            }
            psA += __shfl_xor_sync(0xffffffffu, psA, 1);
            psA += __shfl_xor_sync(0xffffffffu, psA, 2);
            psB += __shfl_xor_sync(0xffffffffu, psB, 1);
            psB += __shfl_xor_sync(0xffffffffu, psB, 2);
            lA[mt] = lA[mt] * corrA + psA;
            lB[mt] = lB[mt] * corrB + psB;
            #pragma unroll
            for (int nt = 0; nt < 8; nt++) {
                acc[mt][nt][0] *= corrA; acc[mt][nt][1] *= corrA;
                acc[mt][nt][2] *= corrB; acc[mt][nt][3] *= corrB;
            }
        }

        // ---- acc += P @ V  (A-operands direct from registers, permuted K) ----
        // A-fragment for k-block ks: (a0,a1,a2,a3) = (p0, p2, p1, p3) of score
        // tile ks; Vs rows were staged with the matching permutation.
        #pragma unroll
        for (int ks = 0; ks < 4; ks++) {
            int k0 = ks * 8;
            unsigned aP[2][4];
            #pragma unroll
            for (int mt = 0; mt < 2; mt++) {
                aP[mt][0] = __float_as_uint(sc[mt][ks][0]);
                aP[mt][1] = __float_as_uint(sc[mt][ks][2]);
                aP[mt][2] = __float_as_uint(sc[mt][ks][1]);
                aP[mt][3] = __float_as_uint(sc[mt][ks][3]);
            }
            #pragma unroll
            for (int nt = 0; nt < 8; nt++) {
                int e0 = nt * 8;
                unsigned b0 = Vs[(k0 + c)     * 72 + e0 + g];
                unsigned b1 = Vs[(k0 + 4 + c) * 72 + e0 + g];
                mma_tf32(acc[0][nt], aP[0], b0, b1);
                mma_tf32(acc[1][nt], aP[1], b0, b1);
            }
        }
    }

    // epilogue: store unnormalized acc + (m,l)
    #pragma unroll
    for (int mt = 0; mt < 2; mt++) {
        int rA = row0 + wrow + mt * 16 + g;
        int rB = rA + 8;
        float* obase = Oacc + (size_t)z * MQ * D_;
        #pragma unroll
        for (int nt = 0; nt < 8; nt++) {
            int col = h * E_ + nt * 8 + 2 * c;
            *(float2*)&obase[(size_t)rA * D_ + col] =
                make_float2(acc[mt][nt][0], acc[mt][nt][1]);
            *(float2*)&obase[(size_t)rB * D_ + col] =
                make_float2(acc[mt][nt][2], acc[mt][nt][3]);
        }
        if (c == 0) {
            size_t iA = ((size_t)(z * MQ + rA) * H_ + h) * 2;
            size_t iB = ((size_t)(z * MQ + rB) * H_ + h) * 2;
            ML[iA]     = mA[mt]; ML[iA + 1] = lA[mt];
            ML[iB]     = mB[mt]; ML[iB + 1] = lB[mt];
        }
    }
}

// ---------------------------------------------------------------------------
// Split-KV combine + mean-pool over TQ=8: (3,2048,768) -> (256,768)
// ---------------------------------------------------------------------------
__global__ void combine_pool_kernel(const float* __restrict__ Oacc,
                                    const float* __restrict__ ML,
                                    float* __restrict__ P) {
    int idx = blockIdx.x * 256 + threadIdx.x;
    if (idx >= BLn * D_) return;
    int bl = idx / D_, d = idx % D_;
    int h = d >> 6;
    float s = 0.f;
    #pragma unroll
    for (int tq = 0; tq < TQn; tq++) {
        int row = bl * TQn + tq;
        size_t i0 = ((size_t)(0 * MQ + row) * H_ + h) * 2;
        size_t i1 = ((size_t)(1 * MQ + row) * H_ + h) * 2;
        size_t i2 = ((size_t)(2 * MQ + row) * H_ + h) * 2;
        float m0 = ML[i0], l0 = ML[i0 + 1];
        float m1 = ML[i1], l1 = ML[i1 + 1];
        float m2 = ML[i2], l2 = ML[i2 + 1];
        float M = fmaxf(m0, fmaxf(m1, m2));
        float w0 = __expf(m0 - M), w1 = __expf(m1 - M), w2 = __expf(m2 - M);
        float denom = l0 * w0 + l1 * w1 + l2 * w2;
        float a0 = Oacc[(size_t)(0 * MQ + row) * D_ + d];
        float a1 = Oacc[(size_t)(1 * MQ + row) * D_ + d];
        float a2 = Oacc[(size_t)(2 * MQ + row) * D_ + d];
        s += (a0 * w0 + a1 * w1 + a2 * w2) / denom;
    }
    P[idx] = s * (1.0f / TQn);
}

// ---------------------------------------------------------------------------
extern "C" void kernel_launch(void* const* d_in, const int* in_sizes, int n_in,
                              void* d_out, int out_size) {
    const float* target     = (const float*)d_in[0];
    const float* key_bank   = (const float*)d_in[1];
    const float* value_bank = (const float*)d_in[2];
    const int*   bank_mask  = (const int*)  d_in[3];
    const float* Wq = (const float*)d_in[4];
    const float* bq = (const float*)d_in[5];
    const float* Wk = (const float*)d_in[6];
    const float* bk = (const float*)d_in[7];
    const float* Wv = (const float*)d_in[8];
    const float* bv = (const float*)d_in[9];
    const float* Wo = (const float*)d_in[10];
    const float* bo = (const float*)d_in[11];
    const float* gq = (const float*)d_in[12];
    const float* betaq = (const float*)d_in[13];
    const float* gkv = (const float*)d_in[14];
    const float* betakv = (const float*)d_in[15];
    float* out = (float*)d_out;

    float *Xq, *Xk, *Xv, *Qb, *Kb, *Vb, *Oacc, *ML, *Pool;
    cudaGetSymbolAddress((void**)&Xq,  g_Xq);
    cudaGetSymbolAddress((void**)&Xk,  g_Xk);
    cudaGetSymbolAddress((void**)&Xv,  g_Xv);
    cudaGetSymbolAddress((void**)&Qb,  g_Qb);
    cudaGetSymbolAddress((void**)&Kb,  g_Kb);
    cudaGetSymbolAddress((void**)&Vb,  g_Vb);
    cudaGetSymbolAddress((void**)&Oacc, g_Oacc);
    cudaGetSymbolAddress((void**)&ML,  g_ML);
    cudaGetSymbolAddress((void**)&Pool, g_Pool);

    cudaFuncSetAttribute(attn_tf32,
                         cudaFuncAttributeMaxDynamicSharedMemorySize, ATTN_SMEM);

    // 1. LayerNorms
    ln_kernel<<<MQ, 256>>>(target, Xq, gq, betaq);
    ln_kernel<<<S_, 256>>>(key_bank, Xk, gkv, betakv);
    ln_kernel<<<S_, 256>>>(value_bank, Xv, gkv, betakv);

    // 2. Q/K/V projections in one batched launch (288 CTAs)
    gemm3_tf32<<<dim3(D_ / 128, 16, 3), 256>>>(
        Xq, Wq, bq, Qb, MQ,
        Xk, Wk, bk, Kb, S_,
        Xv, Wv, bv, Vb, S_);

    // 3. Attention: split-KV x3, occ 2 => 288 CTAs in ONE wave
    attn_tf32<<<dim3(MQ / AQT, H_, NSPLIT), 256, ATTN_SMEM>>>(
        Qb, Kb, Vb, bank_mask, Oacc, ML);

    // 4. Combine splits + mean-pool over TQ
    combine_pool_kernel<<<(BLn * D_ + 255) / 256, 256>>>(Oacc, ML, Pool);

    // 5. Output projection
    gemm3_tf32<<<dim3(D_ / 128, 2, 1), 256>>>(
        Pool, Wo, bo, out, BLn,
        Pool, Wo, bo, out, BLn,
        Pool, Wo, bo, out, BLn);
}